// round 11
// baseline (speedup 1.0000x reference)
#include <cuda_runtime.h>
#include <math.h>

#define BB 8
#define SS 785
#define DD 128
#define HH 8
#define DHD 64
#define DFF 512
#define LL 6
#define HWP 784
#define CINC 512
#define BSR (BB*SS)   // 6280

// ------------------------- scratch (device globals) -------------------------
__device__ float g_xs[BSR*DD];     // raw fp32 stream (residual/head)
__device__ float g_xsr[BSR*DD];    // tf32-rounded copy of xs (GEMM A operand)
__device__ float g_xf[BSR*DD];     // fixed stream, tf32-rounded after assemble
__device__ float g_q[BSR*512];
__device__ float g_k[BSR*512];
__device__ float g_v[BSR*512];
__device__ float g_s512[BSR*512];
__device__ float g_wt[CINC*DD];
__device__ float g_tb[DD];
__device__ unsigned g_maxbits;
#define WSEG (LL*DD*512)          // 393216
__device__ float g_wr[6*WSEG];    // rounded weights: Wq,Wk,Wv,Wo,fw1,fw2

// --------------------------- helpers ----------------------------------------
__device__ __forceinline__ unsigned tf32c(float x) {
    unsigned u;
    asm("cvt.rna.tf32.f32 %0, %1;" : "=r"(u) : "f"(x));
    return u;
}
__device__ __forceinline__ float rnd_tf32(float x) {
    return __uint_as_float(tf32c(x));
}
__device__ __forceinline__ void mma8(float* c, const unsigned* a, const unsigned* b) {
    asm volatile(
        "mma.sync.aligned.m16n8k8.row.col.f32.tf32.tf32.f32 "
        "{%0,%1,%2,%3}, {%4,%5,%6,%7}, {%8,%9}, {%0,%1,%2,%3};"
        : "+f"(c[0]), "+f"(c[1]), "+f"(c[2]), "+f"(c[3])
        : "r"(a[0]), "r"(a[1]), "r"(a[2]), "r"(a[3]), "r"(b[0]), "r"(b[1]));
}
__device__ __forceinline__ void cpasync16(unsigned* dst, const void* src, int sbytes) {
    unsigned sa = (unsigned)__cvta_generic_to_shared(dst);
    asm volatile("cp.async.cg.shared.global [%0], [%1], 16, %2;"
                 :: "r"(sa), "l"(src), "r"(sbytes) : "memory");
}
#define CP_COMMIT() asm volatile("cp.async.commit_group;" ::: "memory")
#define CP_WAIT1() asm volatile("cp.async.wait_group 1;" ::: "memory")
#define CP_WAIT0() asm volatile("cp.async.wait_group 0;" ::: "memory")

// ------------------------- prep: fold BN into conv W ------------------------
__global__ void prep_kernel(const float* __restrict__ conv_w,
                            const float* __restrict__ gamma,
                            const float* __restrict__ beta,
                            const float* __restrict__ mean,
                            const float* __restrict__ var) {
    int i = blockIdx.x * blockDim.x + threadIdx.x;
    if (i == 0) g_maxbits = 0u;
    if (i < DD) {
        float s = gamma[i] * rsqrtf(var[i] + 1e-5f);
        g_tb[i] = beta[i] - mean[i] * s;
    }
    if (i < CINC * DD) {
        int c = i / DD, d = i % DD;
        float s = gamma[d] * rsqrtf(var[d] + 1e-5f);
        g_wt[i] = conv_w[d * CINC + c] * s;
    }
}

// --------------- pre-round all transformer weights to tf32 ------------------
__global__ void wround_kernel(const float* __restrict__ Wq, const float* __restrict__ Wk,
                              const float* __restrict__ Wv, const float* __restrict__ Wo,
                              const float* __restrict__ f1, const float* __restrict__ f2) {
    int i = blockIdx.x * 256 + threadIdx.x;
    if (i >= WSEG) return;
    g_wr[0*WSEG + i] = rnd_tf32(Wq[i]);
    g_wr[1*WSEG + i] = rnd_tf32(Wk[i]);
    g_wr[2*WSEG + i] = rnd_tf32(Wv[i]);
    g_wr[3*WSEG + i] = rnd_tf32(Wo[i]);
    g_wr[4*WSEG + i] = rnd_tf32(f1[i]);
    g_wr[5*WSEG + i] = rnd_tf32(f2[i]);
}

// ------------------ conv stem: 1x1 conv + BN + relu + max -------------------
__global__ __launch_bounds__(256) void conv_kernel(const float* __restrict__ x,
                                                   const float* __restrict__ y) {
    const int pb = blockIdx.x * 64;
    const int b  = blockIdx.y;
    const int st = blockIdx.z;
    const float* src = (st == 0) ? x : y;
    float* dst = (st == 0) ? g_xs : g_xf;

    __shared__ float Xs[16 * 64];
    __shared__ float Ws[16 * 128];

    const int t  = threadIdx.x;
    const int tx = t & 15;
    const int ty = t >> 4;

    float acc[4][8];
    #pragma unroll
    for (int i = 0; i < 4; i++)
        #pragma unroll
        for (int j = 0; j < 8; j++) acc[i][j] = 0.f;

    for (int c0 = 0; c0 < CINC; c0 += 16) {
        {
            int cc = t >> 4, pp = (t & 15) << 2;
            int p = pb + pp;
            float4 v = make_float4(0.f, 0.f, 0.f, 0.f);
            if (p < HWP)
                v = *(const float4*)&src[((size_t)(b * CINC) + (c0 + cc)) * HWP + p];
            *(float4*)&Xs[cc * 64 + pp] = v;
        }
        {
            int cc = t >> 4, ddv = (t & 15) << 3;
            const float* wp = &g_wt[(c0 + cc) * DD + ddv];
            *(float4*)&Ws[cc * 128 + ddv]     = *(const float4*)(wp);
            *(float4*)&Ws[cc * 128 + ddv + 4] = *(const float4*)(wp + 4);
        }
        __syncthreads();
        #pragma unroll
        for (int kk = 0; kk < 16; kk++) {
            float4 a  = *(float4*)&Xs[kk * 64 + (ty << 2)];
            float4 w0 = *(float4*)&Ws[kk * 128 + (tx << 3)];
            float4 w1 = *(float4*)&Ws[kk * 128 + (tx << 3) + 4];
            float av[4] = {a.x, a.y, a.z, a.w};
            float wv[8] = {w0.x, w0.y, w0.z, w0.w, w1.x, w1.y, w1.z, w1.w};
            #pragma unroll
            for (int i = 0; i < 4; i++)
                #pragma unroll
                for (int j = 0; j < 8; j++) acc[i][j] = fmaf(av[i], wv[j], acc[i][j]);
        }
        __syncthreads();
    }

    float lmax = 0.f;
    #pragma unroll
    for (int i = 0; i < 4; i++) {
        int p = pb + (ty << 2) + i;
        if (p < HWP) {
            #pragma unroll
            for (int j = 0; j < 8; j++) {
                int d = (tx << 3) + j;
                float v = fmaxf(acc[i][j] + g_tb[d], 0.f);
                lmax = fmaxf(lmax, v);
                dst[((size_t)(b * SS) + 1 + p) * DD + d] = v;
            }
        }
    }
    __shared__ float red[256];
    red[t] = lmax;
    __syncthreads();
    for (int stx = 128; stx > 0; stx >>= 1) {
        if (t < stx) red[t] = fmaxf(red[t], red[t + stx]);
        __syncthreads();
    }
    if (t == 0) atomicMax(&g_maxbits, __float_as_uint(red[0]));
}

// -- assemble: cls row, /max, +pos; xs raw + xsr rounded, xf rounded in place -
__global__ void assemble_kernel(const float* __restrict__ pos,
                                const float* __restrict__ cls) {
    int i = blockIdx.x * blockDim.x + threadIdx.x;   // float4 index
    if (i >= BSR * DD / 4) return;
    float inv = 1.f / __uint_as_float(g_maxbits);
    int d4 = (i & 31) << 2;
    int s = (i >> 5) % SS;
    float4 p = *(const float4*)&pos[s * DD + d4];
    float4 vs, vf;
    if (s == 0) {
        float4 c = *(const float4*)&cls[d4];
        vs.x = c.x + p.x; vs.y = c.y + p.y; vs.z = c.z + p.z; vs.w = c.w + p.w;
        vf = vs;
    } else {
        float4 a = *(float4*)&g_xs[(size_t)i * 4];
        float4 b = *(float4*)&g_xf[(size_t)i * 4];
        vs.x = a.x * inv + p.x; vs.y = a.y * inv + p.y;
        vs.z = a.z * inv + p.z; vs.w = a.w * inv + p.w;
        vf.x = b.x * inv + p.x; vf.y = b.y * inv + p.y;
        vf.z = b.z * inv + p.z; vf.w = b.w * inv + p.w;
    }
    *(float4*)&g_xs[(size_t)i * 4] = vs;
    float4 vr;
    vr.x = rnd_tf32(vs.x); vr.y = rnd_tf32(vs.y);
    vr.z = rnd_tf32(vs.z); vr.w = rnd_tf32(vs.w);
    *(float4*)&g_xsr[(size_t)i * 4] = vr;
    vf.x = rnd_tf32(vf.x); vf.y = rnd_tf32(vf.y);
    vf.z = rnd_tf32(vf.z); vf.w = rnd_tf32(vf.w);
    *(float4*)&g_xf[(size_t)i * 4] = vf;
}

// ===================== tf32 tensor-core GEMM machinery ======================
// tile 64(M) x 128(N), BK=32, 128 threads (4 warps), warp tile 32x64,
// cp.async double-buffered; operands are pre-rounded tf32 values in fp32 slots.
#define SA 36
#define SB 136
#define ASZ (64 * SA)
#define BSZ (32 * SB)
#define GEMM_SMEM ((2 * ASZ + 2 * BSZ) * 4)

__device__ __forceinline__ void g_stage(unsigned* As, unsigned* Bs,
                                        const float* A, const float* Bm,
                                        int m0, int n0, int M, int N, int K,
                                        int k0, int t) {
    #pragma unroll
    for (int p = 0; p < 4; p++) {
        int id = t + p * 128, row = id >> 3, c4 = (id & 7) << 2;
        int gr = m0 + row;
        int ok = (gr < M) ? 16 : 0;
        const float* src = &A[(size_t)((gr < M) ? gr : M - 1) * K + k0 + c4];
        cpasync16(&As[row * SA + c4], src, ok);
    }
    #pragma unroll
    for (int p = 0; p < 8; p++) {
        int id = t + p * 128, row = id >> 5, col = (id & 31) << 2;
        cpasync16(&Bs[row * SB + col], &Bm[(size_t)(k0 + row) * N + n0 + col], 16);
    }
}

__device__ __forceinline__ void mma_tile(const unsigned* As, const unsigned* Bs,
                                         float acc[2][8][4], int wm, int wn,
                                         int group, int tig) {
    const int colbase = wn * 64 + group;
    #pragma unroll
    for (int kk = 0; kk < 32; kk += 8) {
        unsigned af[2][4];
        #pragma unroll
        for (int mi = 0; mi < 2; mi++) {
            int base = wm * 32 + mi * 16 + group;
            af[mi][0] = As[base * SA + kk + tig];
            af[mi][1] = As[(base + 8) * SA + kk + tig];
            af[mi][2] = As[base * SA + kk + tig + 4];
            af[mi][3] = As[(base + 8) * SA + kk + tig + 4];
        }
        unsigned bf[8][2];
        #pragma unroll
        for (int ni = 0; ni < 8; ni++) {
            bf[ni][0] = Bs[(kk + tig) * SB + colbase + ni * 8];
            bf[ni][1] = Bs[(kk + tig + 4) * SB + colbase + ni * 8];
        }
        #pragma unroll
        for (int mi = 0; mi < 2; mi++)
            #pragma unroll
            for (int ni = 0; ni < 8; ni++)
                mma8(acc[mi][ni], af[mi], bf[ni]);
    }
}

// main-loop helper: accumulate A[m0:m0+64, kbeg:kbeg+32*nit] @ B into acc
__device__ __forceinline__ void gemm_main(float acc[2][8][4],
                                          const float* A, const float* Bm,
                                          int M, int N, int K,
                                          int m0, int n0, int kbeg, int nit) {
    extern __shared__ unsigned sm[];
    unsigned* Asb = sm;
    unsigned* Bsb = sm + 2 * ASZ;
    const int t = threadIdx.x;
    g_stage(Asb, Bsb, A, Bm, m0, n0, M, N, K, kbeg, t);
    CP_COMMIT();
    for (int it = 0; it < nit; it++) {
        int cur = it & 1;
        bool more = (it + 1) < nit;
        if (more) {
            int nxt = cur ^ 1;
            g_stage(Asb + nxt * ASZ, Bsb + nxt * BSZ, A, Bm, m0, n0, M, N, K,
                    kbeg + (it + 1) * 32, t);
            CP_COMMIT();
            CP_WAIT1();
        } else {
            CP_WAIT0();
        }
        __syncthreads();
        {
            const int lane = t & 31, w = t >> 5;
            mma_tile(Asb + cur * ASZ, Bsb + cur * BSZ, acc,
                     w & 1, w >> 1, lane >> 2, lane & 3);
        }
        __syncthreads();
    }
}

template <int ACT, int RND>
__device__ __forceinline__ void gemm_body(const float* A, const float* Bm,
                                          const float* bias, float* C,
                                          int M, int N, int K,
                                          int m0, int n0, int kbeg, int nit) {
    const int t = threadIdx.x;
    const int lane = t & 31, w = t >> 5;
    const int group = lane >> 2, tig = lane & 3;
    const int wm = w & 1, wn = w >> 1;

    float acc[2][8][4];
    #pragma unroll
    for (int mi = 0; mi < 2; mi++)
        #pragma unroll
        for (int ni = 0; ni < 8; ni++)
            #pragma unroll
            for (int r = 0; r < 4; r++) acc[mi][ni][r] = 0.f;

    gemm_main(acc, A, Bm, M, N, K, m0, n0, kbeg, nit);

    #pragma unroll
    for (int mi = 0; mi < 2; mi++) {
        int row0 = m0 + wm * 32 + mi * 16 + group;
        #pragma unroll
        for (int ni = 0; ni < 8; ni++) {
            int col = n0 + wn * 64 + ni * 8 + tig * 2;
            float b0 = bias[col], b1 = bias[col + 1];
            float v0 = acc[mi][ni][0] + b0, v1 = acc[mi][ni][1] + b1;
            float v2 = acc[mi][ni][2] + b0, v3 = acc[mi][ni][3] + b1;
            if (ACT == 1) {
                v0 = v0 * normcdff(v0); v1 = v1 * normcdff(v1);
                v2 = v2 * normcdff(v2); v3 = v3 * normcdff(v3);
            }
            if (RND == 1) {
                v0 = rnd_tf32(v0); v1 = rnd_tf32(v1);
                v2 = rnd_tf32(v2); v3 = rnd_tf32(v3);
            }
            if (row0 < M)
                *(float2*)&C[(size_t)row0 * N + col] = make_float2(v0, v1);
            if (row0 + 8 < M)
                *(float2*)&C[(size_t)(row0 + 8) * N + col] = make_float2(v2, v3);
        }
    }
}

// merged QKV projection: grid (4, 99, 3), outputs rounded to tf32
struct QKVArgs {
    const float* A[3];
    const float* B[3];
    const float* bias[3];
    float* C[3];
};
__global__ __launch_bounds__(128) void gemm_qkv_kernel(QKVArgs args) {
    int z = blockIdx.z;
    gemm_body<0, 1>(args.A[z], args.B[z], args.bias[z], args.C[z],
                    BSR, 512, 128, blockIdx.y * 64, blockIdx.x * 128, 0, 4);
}

// ffn1: GELU, N=512, K=128, output rounded (consumed by ffn2 GEMM)
__global__ __launch_bounds__(128) void gemm_ffn1_kernel(const float* A, const float* Bm,
                                                        const float* bias, float* C) {
    gemm_body<1, 1>(A, Bm, bias, C, BSR, 512, 128,
                    blockIdx.y * 64, blockIdx.x * 128, 0, 4);
}

// ---- fused GEMM (K=512, N=128) + residual + bias + LayerNorm ---------------
// One block owns 64 full rows -> LN reduction is block-local.
// Writes g_xs (raw) and g_xsr (tf32-rounded) in place.
__global__ __launch_bounds__(128) void gemm_ln_kernel(const float* __restrict__ A,
                                                      const float* __restrict__ Bm,
                                                      const float* __restrict__ bias,
                                                      const float* __restrict__ gw,
                                                      const float* __restrict__ bw) {
    __shared__ float redS[64][2];
    __shared__ float redQ[64][2];
    const int t = threadIdx.x;
    const int lane = t & 31, w = t >> 5;
    const int group = lane >> 2, tig = lane & 3;
    const int wm = w & 1, wn = w >> 1;
    const int m0 = blockIdx.y * 64;
    const int M = BSR, N = 128;

    float acc[2][8][4];
    #pragma unroll
    for (int mi = 0; mi < 2; mi++)
        #pragma unroll
        for (int ni = 0; ni < 8; ni++)
            #pragma unroll
            for (int r = 0; r < 4; r++) acc[mi][ni][r] = 0.f;

    gemm_main(acc, A, Bm, M, N, 512, m0, 0, 0, 16);

    // v = acc + residual + bias; accumulate sum and sumsq per row
    float s[2][2], q[2][2];
    #pragma unroll
    for (int mi = 0; mi < 2; mi++) {
        int row0 = m0 + wm * 32 + mi * 16 + group;
        int r0 = (row0 < M) ? row0 : M - 1;
        int r1 = (row0 + 8 < M) ? row0 + 8 : M - 1;
        s[mi][0] = 0.f; s[mi][1] = 0.f; q[mi][0] = 0.f; q[mi][1] = 0.f;
        #pragma unroll
        for (int ni = 0; ni < 8; ni++) {
            int col = wn * 64 + ni * 8 + tig * 2;
            float2 x0 = *(const float2*)&g_xs[(size_t)r0 * DD + col];
            float2 x1 = *(const float2*)&g_xs[(size_t)r1 * DD + col];
            float b0 = bias[col], b1 = bias[col + 1];
            float v0 = acc[mi][ni][0] + x0.x + b0;
            float v1 = acc[mi][ni][1] + x0.y + b1;
            float v2 = acc[mi][ni][2] + x1.x + b0;
            float v3 = acc[mi][ni][3] + x1.y + b1;
            acc[mi][ni][0] = v0; acc[mi][ni][1] = v1;
            acc[mi][ni][2] = v2; acc[mi][ni][3] = v3;
            s[mi][0] += v0 + v1; q[mi][0] += v0 * v0 + v1 * v1;
            s[mi][1] += v2 + v3; q[mi][1] += v2 * v2 + v3 * v3;
        }
    }
    // reduce across tig (lane bits 0..1)
    #pragma unroll
    for (int mi = 0; mi < 2; mi++)
        #pragma unroll
        for (int hf = 0; hf < 2; hf++) {
            float sv = s[mi][hf], qv = q[mi][hf];
            sv += __shfl_xor_sync(~0u, sv, 1);
            sv += __shfl_xor_sync(~0u, sv, 2);
            qv += __shfl_xor_sync(~0u, qv, 1);
            qv += __shfl_xor_sync(~0u, qv, 2);
            if (tig == 0) {
                int r = wm * 32 + mi * 16 + group + hf * 8;
                redS[r][wn] = sv;
                redQ[r][wn] = qv;
            }
        }
    __syncthreads();
    // final LN params per row and write-out
    #pragma unroll
    for (int mi = 0; mi < 2; mi++) {
        int rl0 = wm * 32 + mi * 16 + group;
        float mu[2], rstd[2];
        #pragma unroll
        for (int hf = 0; hf < 2; hf++) {
            int r = rl0 + hf * 8;
            float S = redS[r][0] + redS[r][1];
            float Q = redQ[r][0] + redQ[r][1];
            float m = S * (1.f / 128.f);
            float var = Q * (1.f / 128.f) - m * m;
            mu[hf] = m;
            rstd[hf] = rsqrtf(var + 1e-12f);
        }
        int row0 = m0 + rl0;
        #pragma unroll
        for (int ni = 0; ni < 8; ni++) {
            int col = wn * 64 + ni * 8 + tig * 2;
            float g0 = gw[col], g1 = gw[col + 1];
            float o0 = bw[col], o1 = bw[col + 1];
            float y0 = (acc[mi][ni][0] - mu[0]) * rstd[0] * g0 + o0;
            float y1 = (acc[mi][ni][1] - mu[0]) * rstd[0] * g1 + o1;
            float y2 = (acc[mi][ni][2] - mu[1]) * rstd[1] * g0 + o0;
            float y3 = (acc[mi][ni][3] - mu[1]) * rstd[1] * g1 + o1;
            if (row0 < M) {
                *(float2*)&g_xs[(size_t)row0 * DD + col] = make_float2(y0, y1);
                *(float2*)&g_xsr[(size_t)row0 * DD + col] =
                    make_float2(rnd_tf32(y0), rnd_tf32(y1));
            }
            if (row0 + 8 < M) {
                *(float2*)&g_xs[(size_t)(row0 + 8) * DD + col] = make_float2(y2, y3);
                *(float2*)&g_xsr[(size_t)(row0 + 8) * DD + col] =
                    make_float2(rnd_tf32(y2), rnd_tf32(y3));
            }
        }
    }
}

// --------------- fused flash attention, tf32 tensor cores -------------------
// grid (13, H, B), 128 threads. K natural layout via cp.async double buffer;
// V transposed via register prefetch; P rounded RNA; output rounded to tf32.
#define SKD 68
#define KSZ (64 * SKD)
#define ATTN_SMEM ((5 * KSZ + 128) * 4)
__global__ __launch_bounds__(128) void attn_kernel(const int* __restrict__ enc) {
    extern __shared__ unsigned dsm[];
    unsigned* KsB = dsm;                // [2][64][68] natural [key][d]
    unsigned* VtB = dsm + 2 * KSZ;      // [2][64][68] transposed [d][key]
    unsigned* Ps  = dsm + 4 * KSZ;      // [64][68]
    float* maskB  = (float*)(dsm + 5 * KSZ);  // [2][64]

    const int qt = blockIdx.x, h = blockIdx.y, b = blockIdx.z;
    const int t = threadIdx.x;
    const int lane = t & 31, w = t >> 5;
    const int group = lane >> 2, tig = lane & 3;

    // Q fragments (already tf32-rounded in g_q)
    unsigned qa[8][4];
    {
        int r0 = qt * 64 + w * 16 + group;
        int s0 = (r0 < SS) ? r0 : SS - 1;
        int s1 = (r0 + 8 < SS) ? r0 + 8 : SS - 1;
        const float* q0p = &g_q[(size_t)(b * SS + s0) * 512 + h * 64];
        const float* q1p = &g_q[(size_t)(b * SS + s1) * 512 + h * 64];
        #pragma unroll
        for (int ks = 0; ks < 8; ks++) {
            int col = ks * 8 + tig;
            qa[ks][0] = __float_as_uint(q0p[col]);
            qa[ks][1] = __float_as_uint(q1p[col]);
            qa[ks][2] = __float_as_uint(q0p[col + 4]);
            qa[ks][3] = __float_as_uint(q1p[col + 4]);
        }
    }

    float mv0 = -1e30f, mv1 = -1e30f, l0 = 0.f, l1 = 0.f;
    float o[8][4];
    #pragma unroll
    for (int dn = 0; dn < 8; dn++)
        #pragma unroll
        for (int r = 0; r < 4; r++) o[dn][r] = 0.f;
    const float scale = 0.125f;
    const int prow = w * 16 + group;
    const int vj = t >> 1, vdh = (t & 1) * 32;

    float4 vreg[8];
    float mreg;

    auto issueK = [&](unsigned* Ks, int t0) {
        #pragma unroll
        for (int p = 0; p < 8; p++) {
            int id = t + p * 128, row = id >> 4, col = (id & 15) << 2;
            int s = t0 + row;
            int ok = (s < SS) ? 16 : 0;
            const float* src = &g_k[(size_t)(b * SS + ((s < SS) ? s : SS - 1)) * 512 + h * 64 + col];
            cpasync16(&Ks[row * SKD + col], src, ok);
        }
    };
    auto prefV = [&](int t0) {
        int s = t0 + vj;
        bool ok = s < SS;
        const float* vp = &g_v[(size_t)(b * SS + (ok ? s : SS - 1)) * 512 + h * 64 + vdh];
        #pragma unroll
        for (int i = 0; i < 8; i++)
            vreg[i] = ok ? *(const float4*)(vp + i * 4) : make_float4(0.f, 0.f, 0.f, 0.f);
        mreg = (ok && enc[b * SS + s] != 0) ? 0.f : -1e9f;
    };
    auto storeV = [&](unsigned* Vt, float* mask) {
        #pragma unroll
        for (int i = 0; i < 8; i++) {
            Vt[(vdh + i * 4 + 0) * SKD + vj] = __float_as_uint(vreg[i].x);
            Vt[(vdh + i * 4 + 1) * SKD + vj] = __float_as_uint(vreg[i].y);
            Vt[(vdh + i * 4 + 2) * SKD + vj] = __float_as_uint(vreg[i].z);
            Vt[(vdh + i * 4 + 3) * SKD + vj] = __float_as_uint(vreg[i].w);
        }
        if ((t & 1) == 0) mask[vj] = mreg;
    };

    issueK(KsB, 0);
    CP_COMMIT();
    prefV(0);
    storeV(VtB, maskB);

    const int NT = (SS + 63) / 64;  // 13
    for (int tile = 0; tile < NT; tile++) {
        int cur = tile & 1, nxt = cur ^ 1;
        bool more = (tile + 1) < NT;
        if (more) {
            issueK(KsB + nxt * KSZ, (tile + 1) * 64);
            CP_COMMIT();
            prefV((tile + 1) * 64);
            CP_WAIT1();
        } else {
            CP_WAIT0();
        }
        __syncthreads();
        const unsigned* Ksc = KsB + cur * KSZ;
        const unsigned* Vtc = VtB + cur * KSZ;
        const float* maskv = maskB + cur * 64;

        // S = Q K^T
        float sc[8][4];
        #pragma unroll
        for (int nj = 0; nj < 8; nj++)
            #pragma unroll
            for (int r = 0; r < 4; r++) sc[nj][r] = 0.f;
        #pragma unroll
        for (int ks = 0; ks < 8; ks++) {
            #pragma unroll
            for (int nj = 0; nj < 8; nj++) {
                unsigned bf[2];
                bf[0] = Ksc[(nj * 8 + group) * SKD + ks * 8 + tig];
                bf[1] = Ksc[(nj * 8 + group) * SKD + ks * 8 + tig + 4];
                mma8(sc[nj], qa[ks], bf);
            }
        }

        // scale + mask + online softmax
        float mx0 = -1e30f, mx1 = -1e30f;
        #pragma unroll
        for (int nj = 0; nj < 8; nj++) {
            float mk0 = maskv[nj * 8 + tig * 2];
            float mk1 = maskv[nj * 8 + tig * 2 + 1];
            sc[nj][0] = sc[nj][0] * scale + mk0;
            sc[nj][1] = sc[nj][1] * scale + mk1;
            sc[nj][2] = sc[nj][2] * scale + mk0;
            sc[nj][3] = sc[nj][3] * scale + mk1;
            mx0 = fmaxf(mx0, fmaxf(sc[nj][0], sc[nj][1]));
            mx1 = fmaxf(mx1, fmaxf(sc[nj][2], sc[nj][3]));
        }
        mx0 = fmaxf(mx0, __shfl_xor_sync(~0u, mx0, 1));
        mx0 = fmaxf(mx0, __shfl_xor_sync(~0u, mx0, 2));
        mx1 = fmaxf(mx1, __shfl_xor_sync(~0u, mx1, 1));
        mx1 = fmaxf(mx1, __shfl_xor_sync(~0u, mx1, 2));
        float nm0 = fmaxf(mv0, mx0), nm1 = fmaxf(mv1, mx1);
        float f0 = __expf(mv0 - nm0), f1 = __expf(mv1 - nm1);
        float rs0 = 0.f, rs1 = 0.f;
        #pragma unroll
        for (int nj = 0; nj < 8; nj++) {
            float p0 = rnd_tf32(__expf(sc[nj][0] - nm0));
            float p1 = rnd_tf32(__expf(sc[nj][1] - nm0));
            float p2 = rnd_tf32(__expf(sc[nj][2] - nm1));
            float p3 = rnd_tf32(__expf(sc[nj][3] - nm1));
            rs0 += p0 + p1;
            rs1 += p2 + p3;
            uint2 u0; u0.x = __float_as_uint(p0); u0.y = __float_as_uint(p1);
            uint2 u1; u1.x = __float_as_uint(p2); u1.y = __float_as_uint(p3);
            *(uint2*)&Ps[prow * SKD + nj * 8 + tig * 2] = u0;
            *(uint2*)&Ps[(prow + 8) * SKD + nj * 8 + tig * 2] = u1;
        }
        rs0 += __shfl_xor_sync(~0u, rs0, 1);
        rs0 += __shfl_xor_sync(~0u, rs0, 2);
        rs1 += __shfl_xor_sync(~0u, rs1, 1);
        rs1 += __shfl_xor_sync(~0u, rs1, 2);
        l0 = l0 * f0 + rs0;
        l1 = l1 * f1 + rs1;
        mv0 = nm0; mv1 = nm1;
        #pragma unroll
        for (int dn = 0; dn < 8; dn++) {
            o[dn][0] *= f0; o[dn][1] *= f0;
            o[dn][2] *= f1; o[dn][3] *= f1;
        }
        __syncwarp();

        // O += P V
        #pragma unroll
        for (int ks = 0; ks < 8; ks++) {
            unsigned pa[4];
            pa[0] = Ps[prow * SKD + ks * 8 + tig];
            pa[1] = Ps[(prow + 8) * SKD + ks * 8 + tig];
            pa[2] = Ps[prow * SKD + ks * 8 + tig + 4];
            pa[3] = Ps[(prow + 8) * SKD + ks * 8 + tig + 4];
            #pragma unroll
            for (int dn = 0; dn < 8; dn++) {
                unsigned bf[2];
                bf[0] = Vtc[(dn * 8 + group) * SKD + ks * 8 + tig];
                bf[1] = Vtc[(dn * 8 + group) * SKD + ks * 8 + tig + 4];
                mma8(o[dn], pa, bf);
            }
        }

        if (more) storeV(VtB + nxt * KSZ, maskB + nxt * 64);
        __syncthreads();
    }

    float il0 = 1.f / l0, il1 = 1.f / l1;
    int sq0 = qt * 64 + w * 16 + group;
    #pragma unroll
    for (int dn = 0; dn < 8; dn++) {
        int col = h * 64 + dn * 8 + tig * 2;
        if (sq0 < SS)
            *(float2*)&g_s512[(size_t)(b * SS + sq0) * 512 + col] =
                make_float2(rnd_tf32(o[dn][0] * il0), rnd_tf32(o[dn][1] * il0));
        if (sq0 + 8 < SS)
            *(float2*)&g_s512[(size_t)(b * SS + sq0 + 8) * 512 + col] =
                make_float2(rnd_tf32(o[dn][2] * il1), rnd_tf32(o[dn][3] * il1));
    }
}

// --------------------------------- head -------------------------------------
__global__ void head_kernel(const float* __restrict__ w1,
                            const float* __restrict__ w2,
                            float* __restrict__ out) {
    int b = blockIdx.x, j = threadIdx.x;
    const float* xr = &g_xs[(size_t)(b * SS) * DD];
    float s = 0.f;
    #pragma unroll
    for (int d = 0; d < DD; d++) s = fmaf(xr[d], w1[d * 512 + j], s);
    s = fmaxf(s, 0.f) * w2[j];
    __shared__ float red[512];
    red[j] = s;
    __syncthreads();
    for (int st = 256; st > 0; st >>= 1) {
        if (j < st) red[j] += red[j + st];
        __syncthreads();
    }
    if (j == 0) out[b] = red[0];
}

// ------------------------------ launcher ------------------------------------
extern "C" void kernel_launch(void* const* d_in, const int* in_sizes, int n_in,
                              void* d_out, int out_size) {
    const float* conv_w   = (const float*)d_in[0];
    const float* bn_gamma = (const float*)d_in[1];
    const float* bn_beta  = (const float*)d_in[2];
    const float* bn_mean  = (const float*)d_in[3];
    const float* bn_var   = (const float*)d_in[4];
    const float* pos_emb  = (const float*)d_in[5];
    const float* cls_tok  = (const float*)d_in[6];
    const float* Wq = (const float*)d_in[7];
    const float* bq = (const float*)d_in[8];
    const float* Wk = (const float*)d_in[9];
    const float* bk = (const float*)d_in[10];
    const float* Wv = (const float*)d_in[11];
    const float* bv = (const float*)d_in[12];
    const float* Wo = (const float*)d_in[13];
    const float* bo = (const float*)d_in[14];
    const float* ln1_g = (const float*)d_in[15];
    const float* ln1_b = (const float*)d_in[16];
    const float* fw1 = (const float*)d_in[17];
    const float* fb1 = (const float*)d_in[18];
    const float* fw2 = (const float*)d_in[19];
    const float* fb2 = (const float*)d_in[20];
    const float* ln2_g = (const float*)d_in[21];
    const float* ln2_b = (const float*)d_in[22];
    const float* pw1 = (const float*)d_in[23];
    const float* pw2 = (const float*)d_in[24];
    const int*   enc = (const int*)d_in[25];
    const float* x   = (const float*)d_in[26];
    const float* y   = (const float*)d_in[27];
    float* out = (float*)d_out;

    float *xs, *xsr, *xf, *q, *k, *v, *s512, *wr;
    cudaGetSymbolAddress((void**)&xs,   g_xs);
    cudaGetSymbolAddress((void**)&xsr,  g_xsr);
    cudaGetSymbolAddress((void**)&xf,   g_xf);
    cudaGetSymbolAddress((void**)&q,    g_q);
    cudaGetSymbolAddress((void**)&k,    g_k);
    cudaGetSymbolAddress((void**)&v,    g_v);
    cudaGetSymbolAddress((void**)&s512, g_s512);
    cudaGetSymbolAddress((void**)&wr,   g_wr);

    cudaFuncSetAttribute(attn_kernel, cudaFuncAttributeMaxDynamicSharedMemorySize,
                         ATTN_SMEM);
    cudaFuncSetAttribute(gemm_qkv_kernel, cudaFuncAttributeMaxDynamicSharedMemorySize,
                         GEMM_SMEM);
    cudaFuncSetAttribute(gemm_ffn1_kernel, cudaFuncAttributeMaxDynamicSharedMemorySize,
                         GEMM_SMEM);
    cudaFuncSetAttribute(gemm_ln_kernel, cudaFuncAttributeMaxDynamicSharedMemorySize,
                         GEMM_SMEM);

    prep_kernel<<<(CINC * DD + 255) / 256, 256>>>(conv_w, bn_gamma, bn_beta,
                                                  bn_mean, bn_var);
    wround_kernel<<<(WSEG + 255) / 256, 256>>>(Wq, Wk, Wv, Wo, fw1, fw2);
    conv_kernel<<<dim3(13, BB, 2), 256>>>(x, y);
    assemble_kernel<<<(BSR * DD / 4 + 255) / 256, 256>>>(pos_emb, cls_tok);

    const int MB = (BSR + 63) / 64;  // 99
    const dim3 gqkv(4, MB, 3);
    const dim3 g512(4, MB);
    const dim3 gln(1, MB);

    for (int i = 0; i < LL; i++) {
        QKVArgs qa;
        qa.A[0] = xf; qa.A[1] = xsr; qa.A[2] = xsr;
        qa.B[0] = wr + 0 * WSEG + (size_t)i * DD * 512;
        qa.B[1] = wr + 1 * WSEG + (size_t)i * DD * 512;
        qa.B[2] = wr + 2 * WSEG + (size_t)i * DD * 512;
        qa.bias[0] = bq + i * 512; qa.bias[1] = bk + i * 512; qa.bias[2] = bv + i * 512;
        qa.C[0] = q; qa.C[1] = k; qa.C[2] = v;

        gemm_qkv_kernel<<<gqkv, 128, GEMM_SMEM>>>(qa);
        attn_kernel<<<dim3(13, HH, BB), 128, ATTN_SMEM>>>(enc);
        gemm_ln_kernel<<<gln, 128, GEMM_SMEM>>>(s512, wr + 3 * WSEG + (size_t)i * 512 * DD,
                                                bo + i * DD,
                                                ln1_g + i * DD, ln1_b + i * DD);
        gemm_ffn1_kernel<<<g512, 128, GEMM_SMEM>>>(xsr, wr + 4 * WSEG + (size_t)i * DD * 512,
                                                   fb1 + i * 512, s512);
        gemm_ln_kernel<<<gln, 128, GEMM_SMEM>>>(s512, wr + 5 * WSEG + (size_t)i * 512 * DD,
                                                fb2 + i * DD,
                                                ln2_g + i * DD, ln2_b + i * DD);
    }
    head_kernel<<<BB, 512>>>(pw1, pw2, out);
}

// round 12
// speedup vs baseline: 1.0165x; 1.0165x over previous
#include <cuda_runtime.h>
#include <math.h>

#define BB 8
#define SS 785
#define DD 128
#define HH 8
#define DHD 64
#define DFF 512
#define LL 6
#define HWP 784
#define CINC 512
#define BSR (BB*SS)   // 6280

// ------------------------- scratch (device globals) -------------------------
__device__ float g_xs[BSR*DD];       // raw fp32 stream (residual/head)
__device__ float g_xsr[BSR*DD];      // tf32-rounded copy of xs (GEMM A operand)
__device__ float g_xf[BSR*DD];       // fixed stream, tf32-rounded after assemble
__device__ float g_q[(size_t)LL*BSR*512];  // all-layer Q (precomputed)
__device__ float g_k[BSR*512];
__device__ float g_v[BSR*512];
__device__ float g_s512[BSR*512];
__device__ float g_wt[CINC*DD];
__device__ float g_tb[DD];
__device__ unsigned g_maxbits;
#define WSEG (LL*DD*512)          // 393216
__device__ float g_wr[6*WSEG];    // rounded weights: Wq,Wk,Wv,Wo,fw1,fw2

// --------------------------- helpers ----------------------------------------
__device__ __forceinline__ unsigned tf32c(float x) {
    unsigned u;
    asm("cvt.rna.tf32.f32 %0, %1;" : "=r"(u) : "f"(x));
    return u;
}
__device__ __forceinline__ float rnd_tf32(float x) {
    return __uint_as_float(tf32c(x));
}
__device__ __forceinline__ void mma8(float* c, const unsigned* a, const unsigned* b) {
    asm volatile(
        "mma.sync.aligned.m16n8k8.row.col.f32.tf32.tf32.f32 "
        "{%0,%1,%2,%3}, {%4,%5,%6,%7}, {%8,%9}, {%0,%1,%2,%3};"
        : "+f"(c[0]), "+f"(c[1]), "+f"(c[2]), "+f"(c[3])
        : "r"(a[0]), "r"(a[1]), "r"(a[2]), "r"(a[3]), "r"(b[0]), "r"(b[1]));
}
__device__ __forceinline__ void cpasync16(unsigned* dst, const void* src, int sbytes) {
    unsigned sa = (unsigned)__cvta_generic_to_shared(dst);
    asm volatile("cp.async.cg.shared.global [%0], [%1], 16, %2;"
                 :: "r"(sa), "l"(src), "r"(sbytes) : "memory");
}
#define CP_COMMIT() asm volatile("cp.async.commit_group;" ::: "memory")
#define CP_WAIT1() asm volatile("cp.async.wait_group 1;" ::: "memory")
#define CP_WAIT0() asm volatile("cp.async.wait_group 0;" ::: "memory")

// ------------------------- prep: fold BN into conv W ------------------------
__global__ void prep_kernel(const float* __restrict__ conv_w,
                            const float* __restrict__ gamma,
                            const float* __restrict__ beta,
                            const float* __restrict__ mean,
                            const float* __restrict__ var) {
    int i = blockIdx.x * blockDim.x + threadIdx.x;
    if (i == 0) g_maxbits = 0u;
    if (i < DD) {
        float s = gamma[i] * rsqrtf(var[i] + 1e-5f);
        g_tb[i] = beta[i] - mean[i] * s;
    }
    if (i < CINC * DD) {
        int c = i / DD, d = i % DD;
        float s = gamma[d] * rsqrtf(var[d] + 1e-5f);
        g_wt[i] = conv_w[d * CINC + c] * s;
    }
}

// --------------- pre-round all transformer weights to tf32 ------------------
__global__ void wround_kernel(const float* __restrict__ Wq, const float* __restrict__ Wk,
                              const float* __restrict__ Wv, const float* __restrict__ Wo,
                              const float* __restrict__ f1, const float* __restrict__ f2) {
    int i = blockIdx.x * 256 + threadIdx.x;
    if (i >= WSEG) return;
    g_wr[0*WSEG + i] = rnd_tf32(Wq[i]);
    g_wr[1*WSEG + i] = rnd_tf32(Wk[i]);
    g_wr[2*WSEG + i] = rnd_tf32(Wv[i]);
    g_wr[3*WSEG + i] = rnd_tf32(Wo[i]);
    g_wr[4*WSEG + i] = rnd_tf32(f1[i]);
    g_wr[5*WSEG + i] = rnd_tf32(f2[i]);
}

// ------------------ conv stem: 1x1 conv + BN + relu + max -------------------
__global__ __launch_bounds__(256) void conv_kernel(const float* __restrict__ x,
                                                   const float* __restrict__ y) {
    const int pb = blockIdx.x * 64;
    const int b  = blockIdx.y;
    const int st = blockIdx.z;
    const float* src = (st == 0) ? x : y;
    float* dst = (st == 0) ? g_xs : g_xf;

    __shared__ float Xs[16 * 64];
    __shared__ float Ws[16 * 128];

    const int t  = threadIdx.x;
    const int tx = t & 15;
    const int ty = t >> 4;

    float acc[4][8];
    #pragma unroll
    for (int i = 0; i < 4; i++)
        #pragma unroll
        for (int j = 0; j < 8; j++) acc[i][j] = 0.f;

    for (int c0 = 0; c0 < CINC; c0 += 16) {
        {
            int cc = t >> 4, pp = (t & 15) << 2;
            int p = pb + pp;
            float4 v = make_float4(0.f, 0.f, 0.f, 0.f);
            if (p < HWP)
                v = *(const float4*)&src[((size_t)(b * CINC) + (c0 + cc)) * HWP + p];
            *(float4*)&Xs[cc * 64 + pp] = v;
        }
        {
            int cc = t >> 4, ddv = (t & 15) << 3;
            const float* wp = &g_wt[(c0 + cc) * DD + ddv];
            *(float4*)&Ws[cc * 128 + ddv]     = *(const float4*)(wp);
            *(float4*)&Ws[cc * 128 + ddv + 4] = *(const float4*)(wp + 4);
        }
        __syncthreads();
        #pragma unroll
        for (int kk = 0; kk < 16; kk++) {
            float4 a  = *(float4*)&Xs[kk * 64 + (ty << 2)];
            float4 w0 = *(float4*)&Ws[kk * 128 + (tx << 3)];
            float4 w1 = *(float4*)&Ws[kk * 128 + (tx << 3) + 4];
            float av[4] = {a.x, a.y, a.z, a.w};
            float wv[8] = {w0.x, w0.y, w0.z, w0.w, w1.x, w1.y, w1.z, w1.w};
            #pragma unroll
            for (int i = 0; i < 4; i++)
                #pragma unroll
                for (int j = 0; j < 8; j++) acc[i][j] = fmaf(av[i], wv[j], acc[i][j]);
        }
        __syncthreads();
    }

    float lmax = 0.f;
    #pragma unroll
    for (int i = 0; i < 4; i++) {
        int p = pb + (ty << 2) + i;
        if (p < HWP) {
            #pragma unroll
            for (int j = 0; j < 8; j++) {
                int d = (tx << 3) + j;
                float v = fmaxf(acc[i][j] + g_tb[d], 0.f);
                lmax = fmaxf(lmax, v);
                dst[((size_t)(b * SS) + 1 + p) * DD + d] = v;
            }
        }
    }
    __shared__ float red[256];
    red[t] = lmax;
    __syncthreads();
    for (int stx = 128; stx > 0; stx >>= 1) {
        if (t < stx) red[t] = fmaxf(red[t], red[t + stx]);
        __syncthreads();
    }
    if (t == 0) atomicMax(&g_maxbits, __float_as_uint(red[0]));
}

// -- assemble: cls row, /max, +pos; xs raw + xsr rounded, xf rounded in place -
__global__ void assemble_kernel(const float* __restrict__ pos,
                                const float* __restrict__ cls) {
    int i = blockIdx.x * blockDim.x + threadIdx.x;   // float4 index
    if (i >= BSR * DD / 4) return;
    float inv = 1.f / __uint_as_float(g_maxbits);
    int d4 = (i & 31) << 2;
    int s = (i >> 5) % SS;
    float4 p = *(const float4*)&pos[s * DD + d4];
    float4 vs, vf;
    if (s == 0) {
        float4 c = *(const float4*)&cls[d4];
        vs.x = c.x + p.x; vs.y = c.y + p.y; vs.z = c.z + p.z; vs.w = c.w + p.w;
        vf = vs;
    } else {
        float4 a = *(float4*)&g_xs[(size_t)i * 4];
        float4 b = *(float4*)&g_xf[(size_t)i * 4];
        vs.x = a.x * inv + p.x; vs.y = a.y * inv + p.y;
        vs.z = a.z * inv + p.z; vs.w = a.w * inv + p.w;
        vf.x = b.x * inv + p.x; vf.y = b.y * inv + p.y;
        vf.z = b.z * inv + p.z; vf.w = b.w * inv + p.w;
    }
    *(float4*)&g_xs[(size_t)i * 4] = vs;
    float4 vr;
    vr.x = rnd_tf32(vs.x); vr.y = rnd_tf32(vs.y);
    vr.z = rnd_tf32(vs.z); vr.w = rnd_tf32(vs.w);
    *(float4*)&g_xsr[(size_t)i * 4] = vr;
    vf.x = rnd_tf32(vf.x); vf.y = rnd_tf32(vf.y);
    vf.z = rnd_tf32(vf.z); vf.w = rnd_tf32(vf.w);
    *(float4*)&g_xf[(size_t)i * 4] = vf;
}

// ===================== tf32 tensor-core GEMM machinery ======================
// tile 64(M) x 128(N), BK=32, warp tile 32x64 over 4 warps (one warp-group);
// cp.async double-buffered; operands are pre-rounded tf32 values in fp32 slots.
#define SA 36
#define SB 136
#define ASZ (64 * SA)
#define BSZ (32 * SB)
#define SMW (2 * ASZ + 2 * BSZ)          // 13312 words per pipeline
#define GEMM_SMEM (SMW * 4)
#define GEMMLN2_SMEM (2 * SMW * 4)

__device__ __forceinline__ void g_stage(unsigned* As, unsigned* Bs,
                                        const float* A, const float* Bm,
                                        int m0, int n0, int M, int N, int K,
                                        int k0, int t) {
    #pragma unroll
    for (int p = 0; p < 4; p++) {
        int id = t + p * 128, row = id >> 3, c4 = (id & 7) << 2;
        int gr = m0 + row;
        int ok = (gr < M) ? 16 : 0;
        const float* src = &A[(size_t)((gr < M) ? gr : M - 1) * K + k0 + c4];
        cpasync16(&As[row * SA + c4], src, ok);
    }
    #pragma unroll
    for (int p = 0; p < 8; p++) {
        int id = t + p * 128, row = id >> 5, col = (id & 31) << 2;
        cpasync16(&Bs[row * SB + col], &Bm[(size_t)(k0 + row) * N + n0 + col], 16);
    }
}

__device__ __forceinline__ void mma_tile(const unsigned* As, const unsigned* Bs,
                                         float acc[2][8][4], int wm, int wn,
                                         int group, int tig) {
    const int colbase = wn * 64 + group;
    #pragma unroll
    for (int kk = 0; kk < 32; kk += 8) {
        unsigned af[2][4];
        #pragma unroll
        for (int mi = 0; mi < 2; mi++) {
            int base = wm * 32 + mi * 16 + group;
            af[mi][0] = As[base * SA + kk + tig];
            af[mi][1] = As[(base + 8) * SA + kk + tig];
            af[mi][2] = As[base * SA + kk + tig + 4];
            af[mi][3] = As[(base + 8) * SA + kk + tig + 4];
        }
        unsigned bf[8][2];
        #pragma unroll
        for (int ni = 0; ni < 8; ni++) {
            bf[ni][0] = Bs[(kk + tig) * SB + colbase + ni * 8];
            bf[ni][1] = Bs[(kk + tig + 4) * SB + colbase + ni * 8];
        }
        #pragma unroll
        for (int mi = 0; mi < 2; mi++)
            #pragma unroll
            for (int ni = 0; ni < 8; ni++)
                mma8(acc[mi][ni], af[mi], bf[ni]);
    }
}

// main loop over one warp-group's pipeline (tl in [0,128), own smem buffers)
__device__ __forceinline__ void gemm_main(float acc[2][8][4],
                                          const float* A, const float* Bm,
                                          int M, int N, int K,
                                          int m0, int n0, int kbeg, int nit,
                                          unsigned* smb, int tl) {
    unsigned* Asb = smb;
    unsigned* Bsb = smb + 2 * ASZ;
    g_stage(Asb, Bsb, A, Bm, m0, n0, M, N, K, kbeg, tl);
    CP_COMMIT();
    for (int it = 0; it < nit; it++) {
        int cur = it & 1;
        bool more = (it + 1) < nit;
        if (more) {
            int nxt = cur ^ 1;
            g_stage(Asb + nxt * ASZ, Bsb + nxt * BSZ, A, Bm, m0, n0, M, N, K,
                    kbeg + (it + 1) * 32, tl);
            CP_COMMIT();
            CP_WAIT1();
        } else {
            CP_WAIT0();
        }
        __syncthreads();
        {
            const int lane = tl & 31, w = tl >> 5;
            mma_tile(Asb + cur * ASZ, Bsb + cur * BSZ, acc,
                     w & 1, w >> 1, lane >> 2, lane & 3);
        }
        __syncthreads();
    }
}

template <int ACT, int RND>
__device__ __forceinline__ void gemm_body(const float* A, const float* Bm,
                                          const float* bias, float* C,
                                          int M, int N, int K,
                                          int m0, int n0, int kbeg, int nit) {
    extern __shared__ unsigned sm[];
    const int t = threadIdx.x;
    const int lane = t & 31, w = t >> 5;
    const int group = lane >> 2, tig = lane & 3;
    const int wm = w & 1, wn = w >> 1;

    float acc[2][8][4];
    #pragma unroll
    for (int mi = 0; mi < 2; mi++)
        #pragma unroll
        for (int ni = 0; ni < 8; ni++)
            #pragma unroll
            for (int r = 0; r < 4; r++) acc[mi][ni][r] = 0.f;

    gemm_main(acc, A, Bm, M, N, K, m0, n0, kbeg, nit, sm, t);

    #pragma unroll
    for (int mi = 0; mi < 2; mi++) {
        int row0 = m0 + wm * 32 + mi * 16 + group;
        #pragma unroll
        for (int ni = 0; ni < 8; ni++) {
            int col = n0 + wn * 64 + ni * 8 + tig * 2;
            float b0 = bias[col], b1 = bias[col + 1];
            float v0 = acc[mi][ni][0] + b0, v1 = acc[mi][ni][1] + b1;
            float v2 = acc[mi][ni][2] + b0, v3 = acc[mi][ni][3] + b1;
            if (ACT == 1) {
                v0 = v0 * normcdff(v0); v1 = v1 * normcdff(v1);
                v2 = v2 * normcdff(v2); v3 = v3 * normcdff(v3);
            }
            if (RND == 1) {
                v0 = rnd_tf32(v0); v1 = rnd_tf32(v1);
                v2 = rnd_tf32(v2); v3 = rnd_tf32(v3);
            }
            if (row0 < M)
                *(float2*)&C[(size_t)row0 * N + col] = make_float2(v0, v1);
            if (row0 + 8 < M)
                *(float2*)&C[(size_t)(row0 + 8) * N + col] = make_float2(v2, v3);
        }
    }
}

// all-layer Q projection: grid (4, 99, 6); xf is layer-invariant
__global__ __launch_bounds__(128) void gemm_qall_kernel(const float* __restrict__ bqAll) {
    int l = blockIdx.z;
    gemm_body<0, 1>(g_xf, g_wr + 0 * WSEG + (size_t)l * DD * 512,
                    bqAll + l * 512, g_q + (size_t)l * BSR * 512,
                    BSR, 512, 128, blockIdx.y * 64, blockIdx.x * 128, 0, 4);
}

// per-layer K/V projection: grid (4, 99, 2)
__global__ __launch_bounds__(128) void gemm_kv_kernel(const float* __restrict__ Bk,
                                                      const float* __restrict__ Bv,
                                                      const float* __restrict__ bk,
                                                      const float* __restrict__ bv) {
    int z = blockIdx.z;
    gemm_body<0, 1>(g_xsr, z ? Bv : Bk, z ? bv : bk, z ? g_v : g_k,
                    BSR, 512, 128, blockIdx.y * 64, blockIdx.x * 128, 0, 4);
}

// ffn1: GELU, N=512, K=128, output rounded (consumed by ffn2 GEMM)
__global__ __launch_bounds__(128) void gemm_ffn1_kernel(const float* A, const float* Bm,
                                                        const float* bias, float* C) {
    gemm_body<1, 1>(A, Bm, bias, C, BSR, 512, 128,
                    blockIdx.y * 64, blockIdx.x * 128, 0, 4);
}

// ---- fused GEMM (K=512, N=128) + residual + bias + LayerNorm, 2 warp-groups
// wg0 computes K[0:256), wg1 computes K[256:512) in independent pipelines;
// partials combined via smem; wg0 does the LN epilogue. One block = 64 rows.
__global__ __launch_bounds__(256) void gemm_ln2_kernel(const float* __restrict__ A,
                                                       const float* __restrict__ Bm,
                                                       const float* __restrict__ bias,
                                                       const float* __restrict__ gw,
                                                       const float* __restrict__ bw) {
    extern __shared__ unsigned sm[];
    __shared__ float redS[64][2];
    __shared__ float redQ[64][2];
    const int t = threadIdx.x;
    const int wg = t >> 7;          // warp-group 0/1
    const int tl = t & 127;
    const int lane = tl & 31, w = tl >> 5;
    const int group = lane >> 2, tig = lane & 3;
    const int wm = w & 1, wn = w >> 1;
    const int m0 = blockIdx.y * 64;
    const int M = BSR, N = 128;

    float acc[2][8][4];
    #pragma unroll
    for (int mi = 0; mi < 2; mi++)
        #pragma unroll
        for (int ni = 0; ni < 8; ni++)
            #pragma unroll
            for (int r = 0; r < 4; r++) acc[mi][ni][r] = 0.f;

    gemm_main(acc, A, Bm, M, N, 512, m0, 0, wg * 256, 8, sm + wg * SMW, tl);
    __syncthreads();

    // wg1 parks its partial in smem (staging buffers are dead now)
    float* accbuf = (float*)sm;   // 64 x 128 floats = 32 KB
    if (wg == 1) {
        #pragma unroll
        for (int mi = 0; mi < 2; mi++) {
            int rl0 = wm * 32 + mi * 16 + group;
            #pragma unroll
            for (int ni = 0; ni < 8; ni++) {
                int col = wn * 64 + ni * 8 + tig * 2;
                *(float2*)&accbuf[rl0 * 128 + col] =
                    make_float2(acc[mi][ni][0], acc[mi][ni][1]);
                *(float2*)&accbuf[(rl0 + 8) * 128 + col] =
                    make_float2(acc[mi][ni][2], acc[mi][ni][3]);
            }
        }
    }
    __syncthreads();

    // wg0: combine, add residual + bias, per-row sums
    if (wg == 0) {
        float s[2][2], q[2][2];
        #pragma unroll
        for (int mi = 0; mi < 2; mi++) {
            int rl0 = wm * 32 + mi * 16 + group;
            int row0 = m0 + rl0;
            int r0 = (row0 < M) ? row0 : M - 1;
            int r1 = (row0 + 8 < M) ? row0 + 8 : M - 1;
            s[mi][0] = 0.f; s[mi][1] = 0.f; q[mi][0] = 0.f; q[mi][1] = 0.f;
            #pragma unroll
            for (int ni = 0; ni < 8; ni++) {
                int col = wn * 64 + ni * 8 + tig * 2;
                float2 h0 = *(float2*)&accbuf[rl0 * 128 + col];
                float2 h1 = *(float2*)&accbuf[(rl0 + 8) * 128 + col];
                float2 x0 = *(const float2*)&g_xs[(size_t)r0 * DD + col];
                float2 x1 = *(const float2*)&g_xs[(size_t)r1 * DD + col];
                float b0 = bias[col], b1 = bias[col + 1];
                float v0 = (acc[mi][ni][0] + h0.x) + x0.x + b0;
                float v1 = (acc[mi][ni][1] + h0.y) + x0.y + b1;
                float v2 = (acc[mi][ni][2] + h1.x) + x1.x + b0;
                float v3 = (acc[mi][ni][3] + h1.y) + x1.y + b1;
                acc[mi][ni][0] = v0; acc[mi][ni][1] = v1;
                acc[mi][ni][2] = v2; acc[mi][ni][3] = v3;
                s[mi][0] += v0 + v1; q[mi][0] += v0 * v0 + v1 * v1;
                s[mi][1] += v2 + v3; q[mi][1] += v2 * v2 + v3 * v3;
            }
        }
        #pragma unroll
        for (int mi = 0; mi < 2; mi++)
            #pragma unroll
            for (int hf = 0; hf < 2; hf++) {
                float sv = s[mi][hf], qv = q[mi][hf];
                sv += __shfl_xor_sync(~0u, sv, 1);
                sv += __shfl_xor_sync(~0u, sv, 2);
                qv += __shfl_xor_sync(~0u, qv, 1);
                qv += __shfl_xor_sync(~0u, qv, 2);
                if (tig == 0) {
                    int r = wm * 32 + mi * 16 + group + hf * 8;
                    redS[r][wn] = sv;
                    redQ[r][wn] = qv;
                }
            }
    }
    __syncthreads();

    if (wg == 0) {
        #pragma unroll
        for (int mi = 0; mi < 2; mi++) {
            int rl0 = wm * 32 + mi * 16 + group;
            float mu[2], rstd[2];
            #pragma unroll
            for (int hf = 0; hf < 2; hf++) {
                int r = rl0 + hf * 8;
                float S = redS[r][0] + redS[r][1];
                float Q = redQ[r][0] + redQ[r][1];
                float m = S * (1.f / 128.f);
                float var = Q * (1.f / 128.f) - m * m;
                mu[hf] = m;
                rstd[hf] = rsqrtf(var + 1e-12f);
            }
            int row0 = m0 + rl0;
            #pragma unroll
            for (int ni = 0; ni < 8; ni++) {
                int col = wn * 64 + ni * 8 + tig * 2;
                float g0 = gw[col], g1 = gw[col + 1];
                float o0 = bw[col], o1 = bw[col + 1];
                float y0 = (acc[mi][ni][0] - mu[0]) * rstd[0] * g0 + o0;
                float y1 = (acc[mi][ni][1] - mu[0]) * rstd[0] * g1 + o1;
                float y2 = (acc[mi][ni][2] - mu[1]) * rstd[1] * g0 + o0;
                float y3 = (acc[mi][ni][3] - mu[1]) * rstd[1] * g1 + o1;
                if (row0 < M) {
                    *(float2*)&g_xs[(size_t)row0 * DD + col] = make_float2(y0, y1);
                    *(float2*)&g_xsr[(size_t)row0 * DD + col] =
                        make_float2(rnd_tf32(y0), rnd_tf32(y1));
                }
                if (row0 + 8 < M) {
                    *(float2*)&g_xs[(size_t)(row0 + 8) * DD + col] = make_float2(y2, y3);
                    *(float2*)&g_xsr[(size_t)(row0 + 8) * DD + col] =
                        make_float2(rnd_tf32(y2), rnd_tf32(y3));
                }
            }
        }
    }
}

// --------------- fused flash attention, tf32 tensor cores -------------------
// grid (13, H, B), 128 threads. K natural layout via cp.async double buffer;
// V transposed via register prefetch; P rounded RNA; output rounded to tf32.
#define SKD 68
#define KSZ (64 * SKD)
#define ATTN_SMEM ((5 * KSZ + 128) * 4)
__global__ __launch_bounds__(128) void attn_kernel(const int* __restrict__ enc,
                                                   const float* __restrict__ qbuf) {
    extern __shared__ unsigned dsm[];
    unsigned* KsB = dsm;                // [2][64][68] natural [key][d]
    unsigned* VtB = dsm + 2 * KSZ;      // [2][64][68] transposed [d][key]
    unsigned* Ps  = dsm + 4 * KSZ;      // [64][68]
    float* maskB  = (float*)(dsm + 5 * KSZ);  // [2][64]

    const int qt = blockIdx.x, h = blockIdx.y, b = blockIdx.z;
    const int t = threadIdx.x;
    const int lane = t & 31, w = t >> 5;
    const int group = lane >> 2, tig = lane & 3;

    // Q fragments (already tf32-rounded)
    unsigned qa[8][4];
    {
        int r0 = qt * 64 + w * 16 + group;
        int s0 = (r0 < SS) ? r0 : SS - 1;
        int s1 = (r0 + 8 < SS) ? r0 + 8 : SS - 1;
        const float* q0p = &qbuf[(size_t)(b * SS + s0) * 512 + h * 64];
        const float* q1p = &qbuf[(size_t)(b * SS + s1) * 512 + h * 64];
        #pragma unroll
        for (int ks = 0; ks < 8; ks++) {
            int col = ks * 8 + tig;
            qa[ks][0] = __float_as_uint(q0p[col]);
            qa[ks][1] = __float_as_uint(q1p[col]);
            qa[ks][2] = __float_as_uint(q0p[col + 4]);
            qa[ks][3] = __float_as_uint(q1p[col + 4]);
        }
    }

    float mv0 = -1e30f, mv1 = -1e30f, l0 = 0.f, l1 = 0.f;
    float o[8][4];
    #pragma unroll
    for (int dn = 0; dn < 8; dn++)
        #pragma unroll
        for (int r = 0; r < 4; r++) o[dn][r] = 0.f;
    const float scale = 0.125f;
    const int prow = w * 16 + group;
    const int vj = t >> 1, vdh = (t & 1) * 32;

    float4 vreg[8];
    float mreg;

    auto issueK = [&](unsigned* Ks, int t0) {
        #pragma unroll
        for (int p = 0; p < 8; p++) {
            int id = t + p * 128, row = id >> 4, col = (id & 15) << 2;
            int s = t0 + row;
            int ok = (s < SS) ? 16 : 0;
            const float* src = &g_k[(size_t)(b * SS + ((s < SS) ? s : SS - 1)) * 512 + h * 64 + col];
            cpasync16(&Ks[row * SKD + col], src, ok);
        }
    };
    auto prefV = [&](int t0) {
        int s = t0 + vj;
        bool ok = s < SS;
        const float* vp = &g_v[(size_t)(b * SS + (ok ? s : SS - 1)) * 512 + h * 64 + vdh];
        #pragma unroll
        for (int i = 0; i < 8; i++)
            vreg[i] = ok ? *(const float4*)(vp + i * 4) : make_float4(0.f, 0.f, 0.f, 0.f);
        mreg = (ok && enc[b * SS + s] != 0) ? 0.f : -1e9f;
    };
    auto storeV = [&](unsigned* Vt, float* mask) {
        #pragma unroll
        for (int i = 0; i < 8; i++) {
            Vt[(vdh + i * 4 + 0) * SKD + vj] = __float_as_uint(vreg[i].x);
            Vt[(vdh + i * 4 + 1) * SKD + vj] = __float_as_uint(vreg[i].y);
            Vt[(vdh + i * 4 + 2) * SKD + vj] = __float_as_uint(vreg[i].z);
            Vt[(vdh + i * 4 + 3) * SKD + vj] = __float_as_uint(vreg[i].w);
        }
        if ((t & 1) == 0) mask[vj] = mreg;
    };

    issueK(KsB, 0);
    CP_COMMIT();
    prefV(0);
    storeV(VtB, maskB);

    const int NT = (SS + 63) / 64;  // 13
    for (int tile = 0; tile < NT; tile++) {
        int cur = tile & 1, nxt = cur ^ 1;
        bool more = (tile + 1) < NT;
        if (more) {
            issueK(KsB + nxt * KSZ, (tile + 1) * 64);
            CP_COMMIT();
            prefV((tile + 1) * 64);
            CP_WAIT1();
        } else {
            CP_WAIT0();
        }
        __syncthreads();
        const unsigned* Ksc = KsB + cur * KSZ;
        const unsigned* Vtc = VtB + cur * KSZ;
        const float* maskv = maskB + cur * 64;

        // S = Q K^T
        float sc[8][4];
        #pragma unroll
        for (int nj = 0; nj < 8; nj++)
            #pragma unroll
            for (int r = 0; r < 4; r++) sc[nj][r] = 0.f;
        #pragma unroll
        for (int ks = 0; ks < 8; ks++) {
            #pragma unroll
            for (int nj = 0; nj < 8; nj++) {
                unsigned bf[2];
                bf[0] = Ksc[(nj * 8 + group) * SKD + ks * 8 + tig];
                bf[1] = Ksc[(nj * 8 + group) * SKD + ks * 8 + tig + 4];
                mma8(sc[nj], qa[ks], bf);
            }
        }

        // scale + mask + online softmax
        float mx0 = -1e30f, mx1 = -1e30f;
        #pragma unroll
        for (int nj = 0; nj < 8; nj++) {
            float mk0 = maskv[nj * 8 + tig * 2];
            float mk1 = maskv[nj * 8 + tig * 2 + 1];
            sc[nj][0] = sc[nj][0] * scale + mk0;
            sc[nj][1] = sc[nj][1] * scale + mk1;
            sc[nj][2] = sc[nj][2] * scale + mk0;
            sc[nj][3] = sc[nj][3] * scale + mk1;
            mx0 = fmaxf(mx0, fmaxf(sc[nj][0], sc[nj][1]));
            mx1 = fmaxf(mx1, fmaxf(sc[nj][2], sc[nj][3]));
        }
        mx0 = fmaxf(mx0, __shfl_xor_sync(~0u, mx0, 1));
        mx0 = fmaxf(mx0, __shfl_xor_sync(~0u, mx0, 2));
        mx1 = fmaxf(mx1, __shfl_xor_sync(~0u, mx1, 1));
        mx1 = fmaxf(mx1, __shfl_xor_sync(~0u, mx1, 2));
        float nm0 = fmaxf(mv0, mx0), nm1 = fmaxf(mv1, mx1);
        float f0 = __expf(mv0 - nm0), f1 = __expf(mv1 - nm1);
        float rs0 = 0.f, rs1 = 0.f;
        #pragma unroll
        for (int nj = 0; nj < 8; nj++) {
            float p0 = rnd_tf32(__expf(sc[nj][0] - nm0));
            float p1 = rnd_tf32(__expf(sc[nj][1] - nm0));
            float p2 = rnd_tf32(__expf(sc[nj][2] - nm1));
            float p3 = rnd_tf32(__expf(sc[nj][3] - nm1));
            rs0 += p0 + p1;
            rs1 += p2 + p3;
            uint2 u0; u0.x = __float_as_uint(p0); u0.y = __float_as_uint(p1);
            uint2 u1; u1.x = __float_as_uint(p2); u1.y = __float_as_uint(p3);
            *(uint2*)&Ps[prow * SKD + nj * 8 + tig * 2] = u0;
            *(uint2*)&Ps[(prow + 8) * SKD + nj * 8 + tig * 2] = u1;
        }
        rs0 += __shfl_xor_sync(~0u, rs0, 1);
        rs0 += __shfl_xor_sync(~0u, rs0, 2);
        rs1 += __shfl_xor_sync(~0u, rs1, 1);
        rs1 += __shfl_xor_sync(~0u, rs1, 2);
        l0 = l0 * f0 + rs0;
        l1 = l1 * f1 + rs1;
        mv0 = nm0; mv1 = nm1;
        #pragma unroll
        for (int dn = 0; dn < 8; dn++) {
            o[dn][0] *= f0; o[dn][1] *= f0;
            o[dn][2] *= f1; o[dn][3] *= f1;
        }
        __syncwarp();

        // O += P V
        #pragma unroll
        for (int ks = 0; ks < 8; ks++) {
            unsigned pa[4];
            pa[0] = Ps[prow * SKD + ks * 8 + tig];
            pa[1] = Ps[(prow + 8) * SKD + ks * 8 + tig];
            pa[2] = Ps[prow * SKD + ks * 8 + tig + 4];
            pa[3] = Ps[(prow + 8) * SKD + ks * 8 + tig + 4];
            #pragma unroll
            for (int dn = 0; dn < 8; dn++) {
                unsigned bf[2];
                bf[0] = Vtc[(dn * 8 + group) * SKD + ks * 8 + tig];
                bf[1] = Vtc[(dn * 8 + group) * SKD + ks * 8 + tig + 4];
                mma8(o[dn], pa, bf);
            }
        }

        if (more) storeV(VtB + nxt * KSZ, maskB + nxt * 64);
        __syncthreads();
    }

    float il0 = 1.f / l0, il1 = 1.f / l1;
    int sq0 = qt * 64 + w * 16 + group;
    #pragma unroll
    for (int dn = 0; dn < 8; dn++) {
        int col = h * 64 + dn * 8 + tig * 2;
        if (sq0 < SS)
            *(float2*)&g_s512[(size_t)(b * SS + sq0) * 512 + col] =
                make_float2(rnd_tf32(o[dn][0] * il0), rnd_tf32(o[dn][1] * il0));
        if (sq0 + 8 < SS)
            *(float2*)&g_s512[(size_t)(b * SS + sq0 + 8) * 512 + col] =
                make_float2(rnd_tf32(o[dn][2] * il1), rnd_tf32(o[dn][3] * il1));
    }
}

// --------------------------------- head -------------------------------------
__global__ void head_kernel(const float* __restrict__ w1,
                            const float* __restrict__ w2,
                            float* __restrict__ out) {
    int b = blockIdx.x, j = threadIdx.x;
    const float* xr = &g_xs[(size_t)(b * SS) * DD];
    float s = 0.f;
    #pragma unroll
    for (int d = 0; d < DD; d++) s = fmaf(xr[d], w1[d * 512 + j], s);
    s = fmaxf(s, 0.f) * w2[j];
    __shared__ float red[512];
    red[j] = s;
    __syncthreads();
    for (int st = 256; st > 0; st >>= 1) {
        if (j < st) red[j] += red[j + st];
        __syncthreads();
    }
    if (j == 0) out[b] = red[0];
}

// ------------------------------ launcher ------------------------------------
extern "C" void kernel_launch(void* const* d_in, const int* in_sizes, int n_in,
                              void* d_out, int out_size) {
    const float* conv_w   = (const float*)d_in[0];
    const float* bn_gamma = (const float*)d_in[1];
    const float* bn_beta  = (const float*)d_in[2];
    const float* bn_mean  = (const float*)d_in[3];
    const float* bn_var   = (const float*)d_in[4];
    const float* pos_emb  = (const float*)d_in[5];
    const float* cls_tok  = (const float*)d_in[6];
    const float* Wq = (const float*)d_in[7];
    const float* bq = (const float*)d_in[8];
    const float* Wk = (const float*)d_in[9];
    const float* bk = (const float*)d_in[10];
    const float* Wv = (const float*)d_in[11];
    const float* bv = (const float*)d_in[12];
    const float* Wo = (const float*)d_in[13];
    const float* bo = (const float*)d_in[14];
    const float* ln1_g = (const float*)d_in[15];
    const float* ln1_b = (const float*)d_in[16];
    const float* fw1 = (const float*)d_in[17];
    const float* fb1 = (const float*)d_in[18];
    const float* fw2 = (const float*)d_in[19];
    const float* fb2 = (const float*)d_in[20];
    const float* ln2_g = (const float*)d_in[21];
    const float* ln2_b = (const float*)d_in[22];
    const float* pw1 = (const float*)d_in[23];
    const float* pw2 = (const float*)d_in[24];
    const int*   enc = (const int*)d_in[25];
    const float* x   = (const float*)d_in[26];
    const float* y   = (const float*)d_in[27];
    float* out = (float*)d_out;

    float *xsr, *q, *s512, *wr;
    cudaGetSymbolAddress((void**)&xsr,  g_xsr);
    cudaGetSymbolAddress((void**)&q,    g_q);
    cudaGetSymbolAddress((void**)&s512, g_s512);
    cudaGetSymbolAddress((void**)&wr,   g_wr);

    cudaFuncSetAttribute(attn_kernel, cudaFuncAttributeMaxDynamicSharedMemorySize,
                         ATTN_SMEM);
    cudaFuncSetAttribute(gemm_qall_kernel, cudaFuncAttributeMaxDynamicSharedMemorySize,
                         GEMM_SMEM);
    cudaFuncSetAttribute(gemm_kv_kernel, cudaFuncAttributeMaxDynamicSharedMemorySize,
                         GEMM_SMEM);
    cudaFuncSetAttribute(gemm_ffn1_kernel, cudaFuncAttributeMaxDynamicSharedMemorySize,
                         GEMM_SMEM);
    cudaFuncSetAttribute(gemm_ln2_kernel, cudaFuncAttributeMaxDynamicSharedMemorySize,
                         GEMMLN2_SMEM);

    prep_kernel<<<(CINC * DD + 255) / 256, 256>>>(conv_w, bn_gamma, bn_beta,
                                                  bn_mean, bn_var);
    wround_kernel<<<(WSEG + 255) / 256, 256>>>(Wq, Wk, Wv, Wo, fw1, fw2);
    conv_kernel<<<dim3(13, BB, 2), 256>>>(x, y);
    assemble_kernel<<<(BSR * DD / 4 + 255) / 256, 256>>>(pos_emb, cls_tok);

    const int MB = (BSR + 63) / 64;  // 99
    gemm_qall_kernel<<<dim3(4, MB, LL), 128, GEMM_SMEM>>>(bq);

    const dim3 gkv(4, MB, 2);
    const dim3 g512(4, MB);
    const dim3 gln(1, MB);

    for (int i = 0; i < LL; i++) {
        gemm_kv_kernel<<<gkv, 128, GEMM_SMEM>>>(
            wr + 1 * WSEG + (size_t)i * DD * 512,
            wr + 2 * WSEG + (size_t)i * DD * 512,
            bk + i * 512, bv + i * 512);
        attn_kernel<<<dim3(13, HH, BB), 128, ATTN_SMEM>>>(
            enc, q + (size_t)i * BSR * 512);
        gemm_ln2_kernel<<<gln, 256, GEMMLN2_SMEM>>>(
            s512, wr + 3 * WSEG + (size_t)i * 512 * DD,
            bo + i * DD, ln1_g + i * DD, ln1_b + i * DD);
        gemm_ffn1_kernel<<<g512, 128, GEMM_SMEM>>>(
            xsr, wr + 4 * WSEG + (size_t)i * DD * 512, fb1 + i * 512, s512);
        gemm_ln2_kernel<<<gln, 256, GEMMLN2_SMEM>>>(
            s512, wr + 5 * WSEG + (size_t)i * 512 * DD,
            fb2 + i * DD, ln2_g + i * DD, ln2_b + i * DD);
    }
    head_kernel<<<BB, 512>>>(pw1, pw2, out);
}